// round 10
// baseline (speedup 1.0000x reference)
#include <cuda_runtime.h>

// CoincidenceLIFBank: B=32 x T=4096 x D=256.
// Output: [0,B*D) pooled | [B*D,+B*D*T) spikes | +D rw | +D tw | +D beta
//
// NUMERICS FROZEN (passed R6/R9, rel_err 9.89e-4):
//   rw/tw = max(x,0) + logf(1 + expf(-|x|));  sigmoid = 1/(1+expf(-x))
//   beta  = fadd(0.7, fmul(0.295, sigmoid))         (uncontracted)
//   cur   = fadd(fmul(rw, rv), fmul(tw, tv))        (UNcontracted)
//   mp    = fma(beta, m, cur); ms = fadd(mp,-1); p = (mp>=1)
//   m = p ? ms : mp;  s = p ? 1 : 0
// OOB ref now comes from a zero-padded smem row -> rv = 0.0f exactly, same
// value the old select produced. Bit-identical trajectories.
//
// R10 structure: 2 independent chains per thread (d and d+32, same b) to
// overlap the serial FMA chains, plus explicit next-group prefetch of
// ref (LDS) and tgt (LDG) over the current group's chain work.

#define NB 32
#define NT 4096
#define ND 256
#define THRESH 1.0f
#define TILE 128
#define TSTRIDE 132          // floats/row: 16B-aligned, conflict-free 4-phase
#define SREF_N (NT + 256)    // zero-padded tail (delay < 128, +prefetch slack)

__device__ __forceinline__ float softplus_xla(float x) {
    const float u = expf(-fabsf(x));
    return __fadd_rn(fmaxf(x, 0.0f), logf(__fadd_rn(1.0f, u)));
}
__device__ __forceinline__ float sigmoid_xla(float x) {
    return 1.0f / (__fadd_rn(1.0f, expf(-x)));
}

__global__ void __launch_bounds__(32)
lif_bank_kernel(const float* __restrict__ ref,
                const float* __restrict__ tgt,
                const int*   __restrict__ delays,
                const float* __restrict__ rw_raw,
                const float* __restrict__ tw_raw,
                const float* __restrict__ beta_raw,
                float* __restrict__ out)
{
    // 128 single-warp blocks: block -> (b, 64-d group). 4 blocks per b.
    const int lane = threadIdx.x;
    const int b    = blockIdx.x >> 2;
    const int q    = blockIdx.x & 3;
    const int dA   = q * 64 + lane;        // chain A
    const int dB   = dA + 32;              // chain B

    __shared__ float sref[SREF_N];                // ref[b,:] + zero pad
    __shared__ float stA[32][TSTRIDE];            // spike tiles (transpose)
    __shared__ float stB[32][TSTRIDE];

    // ---- stage ref row (coalesced LDG.128) + zero pad ----
    {
        const float4* __restrict__ ref4 = (const float4*)(ref + b * NT);
        float4* s4 = (float4*)sref;
#pragma unroll
        for (int i = 0; i < NT / 128; i++)              // 32 iters: data
            s4[lane + 32 * i] = __ldg(ref4 + lane + 32 * i);
#pragma unroll
        for (int i = NT / 128; i < SREF_N / 128; i++)   // 2 iters: zeros
            s4[lane + 32 * i] = make_float4(0.f, 0.f, 0.f, 0.f);
    }

    // ---- per-chain params (frozen recipe) ----
    const float rwA = softplus_xla(rw_raw[dA]);
    const float twA = softplus_xla(tw_raw[dA]);
    const float beA = __fadd_rn(0.7f, __fmul_rn(0.295f, sigmoid_xla(beta_raw[dA])));
    const int   dlA = delays[dA];
    const float rwB = softplus_xla(rw_raw[dB]);
    const float twB = softplus_xla(tw_raw[dB]);
    const float beB = __fadd_rn(0.7f, __fmul_rn(0.295f, sigmoid_xla(beta_raw[dB])));
    const int   dlB = delays[dB];

    const float* __restrict__ tgtrow = tgt + b * NT;

    float* out_pooled = out;
    float* out_spk    = out + NB * ND;
    float* out_rw     = out + NB * ND + (size_t)NB * ND * NT;
    float* out_tw     = out_rw + ND;
    float* out_beta   = out_tw + ND;

    float mA = 0.f, mB = 0.f, cntA = 0.f, cntB = 0.f;

    __syncwarp();   // sref visible

    // ---- software-pipelined scan: prefetch group g+1 over chain of g ----
    float tv[4], rvA[4], rvB[4];
    {
        const float4 v = __ldg((const float4*)tgtrow);
        tv[0]=v.x; tv[1]=v.y; tv[2]=v.z; tv[3]=v.w;
#pragma unroll
        for (int j = 0; j < 4; j++) { rvA[j] = sref[dlA + j]; rvB[j] = sref[dlB + j]; }
    }

    for (int tile0 = 0; tile0 < NT; tile0 += TILE) {
        for (int t0 = tile0; t0 < tile0 + TILE; t0 += 4) {
            // prefetch next group (pad guarantees in-bounds; last iter unused)
            float ntv[4], nrA[4], nrB[4];
            {
                const int tn = t0 + 4;
                const float4 v = __ldg((const float4*)(tgtrow + (tn < NT ? tn : 0)));
                ntv[0]=v.x; ntv[1]=v.y; ntv[2]=v.z; ntv[3]=v.w;
#pragma unroll
                for (int j = 0; j < 4; j++) {
                    nrA[j] = sref[dlA + tn + j];
                    nrB[j] = sref[dlB + tn + j];
                }
            }

            // two interleaved serial chains (A,B independent -> ILP 2)
            float spA[4], spB[4];
#pragma unroll
            for (int j = 0; j < 4; j++) {
                const float curA = __fadd_rn(__fmul_rn(rwA, rvA[j]), __fmul_rn(twA, tv[j]));
                const float curB = __fadd_rn(__fmul_rn(rwB, rvB[j]), __fmul_rn(twB, tv[j]));
                const float mpA = __fmaf_rn(beA, mA, curA);
                const float mpB = __fmaf_rn(beB, mB, curB);
                const float msA = __fadd_rn(mpA, -THRESH);
                const float msB = __fadd_rn(mpB, -THRESH);
                const bool  pA  = (mpA >= THRESH);
                const bool  pB  = (mpB >= THRESH);
                mA = pA ? msA : mpA;
                mB = pB ? msB : mpB;
                spA[j] = pA ? 1.0f : 0.0f;
                spB[j] = pB ? 1.0f : 0.0f;
                cntA += spA[j];
                cntB += spB[j];
            }

            const int toff = t0 - tile0;
            *(float4*)&stA[lane][toff] = make_float4(spA[0], spA[1], spA[2], spA[3]);
            *(float4*)&stB[lane][toff] = make_float4(spB[0], spB[1], spB[2], spB[3]);

#pragma unroll
            for (int j = 0; j < 4; j++) { tv[j]=ntv[j]; rvA[j]=nrA[j]; rvB[j]=nrB[j]; }
        }
        __syncwarp();

        // ---- dump 64 rows, 512B contiguous STG.128 bursts ----
#pragma unroll 4
        for (int r = 0; r < 32; r++) {
            const float4 wa = *(const float4*)&stA[r][lane * 4];
            float* da = out_spk + (size_t)(b * ND + q * 64 + r) * NT + tile0;
            *(float4*)(da + lane * 4) = wa;
        }
#pragma unroll 4
        for (int r = 0; r < 32; r++) {
            const float4 wb = *(const float4*)&stB[r][lane * 4];
            float* db = out_spk + (size_t)(b * ND + q * 64 + 32 + r) * NT + tile0;
            *(float4*)(db + lane * 4) = wb;
        }
        __syncwarp();
    }

    out_pooled[b * ND + dA] = cntA * (1.0f / NT);
    out_pooled[b * ND + dB] = cntB * (1.0f / NT);

    if (b == 0) {   // blocks 0..3 cover d = 0..255 exactly once
        out_rw[dA] = rwA;  out_tw[dA] = twA;  out_beta[dA] = beA;
        out_rw[dB] = rwB;  out_tw[dB] = twB;  out_beta[dB] = beB;
    }
}

extern "C" void kernel_launch(void* const* d_in, const int* in_sizes, int n_in,
                              void* d_out, int out_size)
{
    const float* ref      = (const float*)d_in[0];
    const float* tgt      = (const float*)d_in[1];
    const int*   delays   = (const int*)  d_in[2];
    const float* rw_raw   = (const float*)d_in[3];
    const float* tw_raw   = (const float*)d_in[4];
    const float* beta_raw = (const float*)d_in[5];
    float* out = (float*)d_out;

    // 128 single-warp blocks, 2 chains per thread, ~50 KB smem each.
    lif_bank_kernel<<<NB * 4, 32>>>(ref, tgt, delays, rw_raw, tw_raw,
                                    beta_raw, out);
}

// round 11
// speedup vs baseline: 3.1541x; 3.1541x over previous
#include <cuda_runtime.h>

// CoincidenceLIFBank: B=32 x T=4096 x D=256.
// Output: [0,B*D) pooled | [B*D,+B*D*T) spikes | +D rw | +D tw | +D beta
//
// NUMERICS FROZEN (passed R6/R9/R10, rel_err 9.894e-4):
//   rw/tw = max(x,0) + logf(1 + expf(-|x|));  sigmoid = 1/(1+expf(-x))
//   beta  = fadd(0.7, fmul(0.295, sigmoid))         (uncontracted)
//   cur   = fadd(fmul(rw, rv), fmul(tw, tv))        (UNcontracted)
//   mp    = fma(beta, m, cur); ms = fadd(mp,-1); p = (mp>=1)
//   m = p ? ms : mp;  s = p ? 1 : 0
// OOB ref reads exact 0.0f from the zero-padded smem row (bit-identical).
//
// R11: the scan loop's ONLY memory is shared memory. Both ref[b,:] and
// tgt[b,:] are staged in smem up front (coalesced); the per-group tgt LDG
// (an exposed ~250cyc L2 hit every 4 steps -- the measured bottleneck in
// R6-R10) is gone. One-group software prefetch covers the 29cyc LDS latency.

#define NB 32
#define NT 4096
#define ND 256
#define THRESH 1.0f
#define TILE 128
#define TSTRIDE 132          // tile row stride: 16B-aligned (528B)
#define SREF_N (NT + 256)    // zero-padded tail (delay < 128 + prefetch slack)

__device__ __forceinline__ float softplus_xla(float x) {
    const float u = expf(-fabsf(x));
    return __fadd_rn(fmaxf(x, 0.0f), logf(__fadd_rn(1.0f, u)));
}
__device__ __forceinline__ float sigmoid_xla(float x) {
    return 1.0f / (__fadd_rn(1.0f, expf(-x)));
}

__global__ void __launch_bounds__(32)
lif_bank_kernel(const float* __restrict__ ref,
                const float* __restrict__ tgt,
                const int*   __restrict__ delays,
                const float* __restrict__ rw_raw,
                const float* __restrict__ tw_raw,
                const float* __restrict__ beta_raw,
                float* __restrict__ out)
{
    // 256 single-warp blocks: block -> (b, 32-d group). 8 blocks per b.
    const int lane = threadIdx.x;
    const int b    = blockIdx.x >> 3;
    const int d0   = (blockIdx.x & 7) * 32;
    const int d    = d0 + lane;

    __shared__ float sref[SREF_N];             // ref[b,:] + zero pad (17 KB)
    __shared__ float stgt[NT];                 // tgt[b,:]            (16 KB)
    __shared__ float stile[32][TSTRIDE];       // spike transpose tile (16.5 KB)

    // ---- stage ref + tgt rows (coalesced warp-wide LDG.128) ----
    {
        const float4* __restrict__ ref4 = (const float4*)(ref + b * NT);
        const float4* __restrict__ tgt4 = (const float4*)(tgt + b * NT);
        float4* sr4 = (float4*)sref;
        float4* st4 = (float4*)stgt;
#pragma unroll
        for (int i = 0; i < NT / 128; i++) {
            sr4[lane + 32 * i] = __ldg(ref4 + lane + 32 * i);
            st4[lane + 32 * i] = __ldg(tgt4 + lane + 32 * i);
        }
#pragma unroll
        for (int i = NT / 128; i < SREF_N / 128; i++)   // zero pad
            sr4[lane + 32 * i] = make_float4(0.f, 0.f, 0.f, 0.f);
    }

    // ---- per-bank params (frozen recipe) ----
    const float rw   = softplus_xla(rw_raw[d]);
    const float tw   = softplus_xla(tw_raw[d]);
    const float beta = __fadd_rn(0.7f, __fmul_rn(0.295f, sigmoid_xla(beta_raw[d])));
    const int   delay = delays[d];

    float* out_pooled = out;
    float* out_spk    = out + NB * ND;
    float* out_rw     = out + NB * ND + (size_t)NB * ND * NT;
    float* out_tw     = out_rw + ND;
    float* out_beta   = out_tw + ND;

    float m = 0.0f;
    float cnt = 0.0f;

    __syncwarp();   // staged rows visible warp-wide

    // ---- software-pipelined scan: all loads are LDS ----
    float tv[4], rv[4];
    {
        const float4 v = *(const float4*)stgt;     // uniform -> broadcast
        tv[0]=v.x; tv[1]=v.y; tv[2]=v.z; tv[3]=v.w;
#pragma unroll
        for (int j = 0; j < 4; j++) rv[j] = sref[delay + j];
    }

    for (int tile0 = 0; tile0 < NT; tile0 += TILE) {
        for (int t0 = tile0; t0 < tile0 + TILE; t0 += 4) {
            // prefetch next group from smem (pad keeps it in-bounds)
            float ntv[4], nrv[4];
            {
                const int tn = t0 + 4;
                const float4 v = *(const float4*)(stgt + (tn & (NT - 1)));
                ntv[0]=v.x; ntv[1]=v.y; ntv[2]=v.z; ntv[3]=v.w;
#pragma unroll
                for (int j = 0; j < 4; j++) nrv[j] = sref[delay + tn + j];
            }

            // serial chain: FMA -> {FADD || FSETP} -> FSEL per step
            float sp[4];
#pragma unroll
            for (int j = 0; j < 4; j++) {
                const float cur = __fadd_rn(__fmul_rn(rw, rv[j]),
                                            __fmul_rn(tw, tv[j]));
                const float mp = __fmaf_rn(beta, m, cur);
                const float ms = __fadd_rn(mp, -THRESH);
                const bool  p  = (mp >= THRESH);
                m = p ? ms : mp;
                sp[j] = p ? 1.0f : 0.0f;
                cnt += sp[j];
            }

            *(float4*)&stile[lane][t0 - tile0] =
                make_float4(sp[0], sp[1], sp[2], sp[3]);

#pragma unroll
            for (int j = 0; j < 4; j++) { tv[j]=ntv[j]; rv[j]=nrv[j]; }
        }
        __syncwarp();

        // ---- dump: 32 rows x 512B contiguous STG.128 bursts ----
#pragma unroll 4
        for (int r = 0; r < 32; r++) {
            const float4 w = *(const float4*)&stile[r][lane * 4];
            float* dst = out_spk + (size_t)(b * ND + d0 + r) * NT + tile0;
            *(float4*)(dst + lane * 4) = w;
        }
        __syncwarp();
    }

    out_pooled[b * ND + d] = cnt * (1.0f / NT);

    if (b == 0) {   // blocks 0..7 cover d = 0..255 exactly once
        out_rw[d]   = rw;
        out_tw[d]   = tw;
        out_beta[d] = beta;
    }
}

extern "C" void kernel_launch(void* const* d_in, const int* in_sizes, int n_in,
                              void* d_out, int out_size)
{
    const float* ref      = (const float*)d_in[0];
    const float* tgt      = (const float*)d_in[1];
    const int*   delays   = (const int*)  d_in[2];
    const float* rw_raw   = (const float*)d_in[3];
    const float* tw_raw   = (const float*)d_in[4];
    const float* beta_raw = (const float*)d_in[5];
    float* out = (float*)d_out;

    // 256 single-warp blocks; ~50 KB smem each; scan loop is smem-only.
    lif_bank_kernel<<<NB * 8, 32>>>(ref, tgt, delays, rw_raw, tw_raw,
                                    beta_raw, out);
}

// round 12
// speedup vs baseline: 3.4692x; 1.0999x over previous
#include <cuda_runtime.h>

// CoincidenceLIFBank: B=32 x T=4096 x D=256.
// Output: [0,B*D) pooled | [B*D,+B*D*T) spikes | +D rw | +D tw | +D beta
//
// NUMERICS FROZEN (rel_err 9.894e-4 across R6-R11):
//   rw/tw = max(x,0) + logf(1 + expf(-|x|));  sigmoid = 1/(1+expf(-x))
//   beta  = fadd(0.7, fmul(0.295, sigmoid))         (uncontracted)
//   cur   = fadd(fmul(rw, rv), fmul(tw, tv))        (UNcontracted)
//   mp    = fma(beta, m, cur); ms = fadd(mp,-1); p = (mp>=1)
//   m = p ? ms : mp;  s = p ? 1 : 0
// OOB ref reads exact 0.0f from the zero-padded smem row.
//
// R12: scheduling only. 8-step inner iterations with ping-pong prefetch
// buffers (no register copies, two short-lived buffer sets) to cut issue
// count and register pressure (R11 hit 254 regs + spills).

#define NB 32
#define NT 4096
#define ND 256
#define THRESH 1.0f
#define TILE 128
#define TSTRIDE 132          // tile row stride in floats (528B, 16B-aligned)
#define SREF_N (NT + 256)    // zero pad: delay<128 + prefetch slack

__device__ __forceinline__ float softplus_xla(float x) {
    const float u = expf(-fabsf(x));
    return __fadd_rn(fmaxf(x, 0.0f), logf(__fadd_rn(1.0f, u)));
}
__device__ __forceinline__ float sigmoid_xla(float x) {
    return 1.0f / (__fadd_rn(1.0f, expf(-x)));
}

// one 4-step LIF group: serial chain, frozen arithmetic
__device__ __forceinline__ void lif4(const float rw, const float tw,
                                     const float beta,
                                     const float* __restrict__ rv,
                                     const float* __restrict__ tv,
                                     float& m, float& cnt,
                                     float* __restrict__ sp)
{
#pragma unroll
    for (int j = 0; j < 4; j++) {
        const float cur = __fadd_rn(__fmul_rn(rw, rv[j]), __fmul_rn(tw, tv[j]));
        const float mp  = __fmaf_rn(beta, m, cur);
        const float ms  = __fadd_rn(mp, -THRESH);
        const bool  p   = (mp >= THRESH);
        m = p ? ms : mp;
        sp[j] = p ? 1.0f : 0.0f;
        cnt += sp[j];
    }
}

__device__ __forceinline__ void fetch4(const float* __restrict__ sref,
                                       const float* __restrict__ stgt,
                                       const int delay, const int t,
                                       float* __restrict__ rv,
                                       float* __restrict__ tv)
{
    const float4 v = *(const float4*)(stgt + (t & (NT - 1)));
    tv[0] = v.x; tv[1] = v.y; tv[2] = v.z; tv[3] = v.w;
#pragma unroll
    for (int j = 0; j < 4; j++) rv[j] = sref[delay + t + j];
}

__global__ void __launch_bounds__(32)
lif_bank_kernel(const float* __restrict__ ref,
                const float* __restrict__ tgt,
                const int*   __restrict__ delays,
                const float* __restrict__ rw_raw,
                const float* __restrict__ tw_raw,
                const float* __restrict__ beta_raw,
                float* __restrict__ out)
{
    // 256 single-warp blocks: block -> (b, 32-d group). 8 blocks per b.
    const int lane = threadIdx.x;
    const int b    = blockIdx.x >> 3;
    const int d0   = (blockIdx.x & 7) * 32;
    const int d    = d0 + lane;

    __shared__ float sref[SREF_N];             // ref[b,:] + zero pad
    __shared__ float stgt[NT];                 // tgt[b,:]
    __shared__ float stile[32][TSTRIDE];       // spike transpose tile

    // ---- stage ref + tgt rows (coalesced warp-wide LDG.128) ----
    {
        const float4* __restrict__ ref4 = (const float4*)(ref + b * NT);
        const float4* __restrict__ tgt4 = (const float4*)(tgt + b * NT);
        float4* sr4 = (float4*)sref;
        float4* st4 = (float4*)stgt;
#pragma unroll
        for (int i = 0; i < NT / 128; i++) {
            sr4[lane + 32 * i] = __ldg(ref4 + lane + 32 * i);
            st4[lane + 32 * i] = __ldg(tgt4 + lane + 32 * i);
        }
#pragma unroll
        for (int i = NT / 128; i < SREF_N / 128; i++)
            sr4[lane + 32 * i] = make_float4(0.f, 0.f, 0.f, 0.f);
    }

    // ---- per-bank params (frozen recipe) ----
    const float rw   = softplus_xla(rw_raw[d]);
    const float tw   = softplus_xla(tw_raw[d]);
    const float beta = __fadd_rn(0.7f, __fmul_rn(0.295f, sigmoid_xla(beta_raw[d])));
    const int   delay = delays[d];

    float* out_pooled = out;
    float* out_spk    = out + NB * ND;
    float* out_rw     = out + NB * ND + (size_t)NB * ND * NT;
    float* out_tw     = out_rw + ND;
    float* out_beta   = out_tw + ND;

    float m = 0.0f;
    float cnt = 0.0f;

    __syncwarp();   // staged rows visible warp-wide

    // ---- ping-pong software pipeline: all loads are LDS ----
    float tvA[4], rvA[4], tvB[4], rvB[4], sp[4];
    fetch4(sref, stgt, delay, 0, rvA, tvA);        // prime buffer A

    for (int tile0 = 0; tile0 < NT; tile0 += TILE) {
        const int toff0 = tile0;
#pragma unroll 2
        for (int t0 = tile0; t0 < tile0 + TILE; t0 += 8) {
            // B <- group t0+4 while chaining group t0 from A
            fetch4(sref, stgt, delay, t0 + 4, rvB, tvB);
            lif4(rw, tw, beta, rvA, tvA, m, cnt, sp);
            *(float4*)&stile[lane][t0 - toff0] =
                make_float4(sp[0], sp[1], sp[2], sp[3]);

            // A <- group t0+8 while chaining group t0+4 from B
            fetch4(sref, stgt, delay, t0 + 8, rvA, tvA);
            lif4(rw, tw, beta, rvB, tvB, m, cnt, sp);
            *(float4*)&stile[lane][t0 + 4 - toff0] =
                make_float4(sp[0], sp[1], sp[2], sp[3]);
        }
        __syncwarp();

        // ---- dump: 32 rows x 512B contiguous STG.128 bursts ----
#pragma unroll 4
        for (int r = 0; r < 32; r++) {
            const float4 w = *(const float4*)&stile[r][lane * 4];
            float* dst = out_spk + (size_t)(b * ND + d0 + r) * NT + tile0;
            *(float4*)(dst + lane * 4) = w;
        }
        __syncwarp();
    }

    out_pooled[b * ND + d] = cnt * (1.0f / NT);

    if (b == 0) {   // blocks 0..7 cover d = 0..255 exactly once
        out_rw[d]   = rw;
        out_tw[d]   = tw;
        out_beta[d] = beta;
    }
}

extern "C" void kernel_launch(void* const* d_in, const int* in_sizes, int n_in,
                              void* d_out, int out_size)
{
    const float* ref      = (const float*)d_in[0];
    const float* tgt      = (const float*)d_in[1];
    const int*   delays   = (const int*)  d_in[2];
    const float* rw_raw   = (const float*)d_in[3];
    const float* tw_raw   = (const float*)d_in[4];
    const float* beta_raw = (const float*)d_in[5];
    float* out = (float*)d_out;

    // 256 single-warp blocks; scan loop touches only smem.
    lif_bank_kernel<<<NB * 8, 32>>>(ref, tgt, delays, rw_raw, tw_raw,
                                    beta_raw, out);
}